// round 15
// baseline (speedup 1.0000x reference)
#include <cuda_runtime.h>
#include <cuda_bf16.h>

#define B_TOT   65536
#define TST     40
#define DT      0.1f
#define MCH     128       // batch rows per CTA
#define NTHR    416       // 13 warps: warp w owns j-tile w (units 8w..8w+7), all 128 rows
#define NPADN   416       // 4 gate blocks x 104 padded units
#define KEL     104       // padded K elems (102 real), 13 chunks of 16B
#define ROWB    208       // operand-image row stride (odd chunk count -> ldsm conflict-free)
#define XKB     808       // xk smem row stride in BYTES (404 bf16; mult of 8)

// ---- SMEM byte offsets (1 CTA/SM, ~166.5 KB) ----
#define OFF_A0   0                 // 128*208 = 26624
#define OFF_A1   26624             // 26624
#define OFF_ATT  53248             // 2 buf * 13*128*4 = 13312
#define OFF_AW   66560             // 100*4 = 400
#define OFF_XK   66960             // xk bf16: 128*808 = 103424 ; ALSO R-image temp (86528) at init
#define SMEM_BYTES 170384

// ---- static device scratch ----
__device__ __align__(16) float         g_xk[(size_t)B_TOT * 400];  // permuted col=4u+g, fp32
__device__ __align__(16) __nv_bfloat16 g_Rimg[NPADN * KEL];        // B image [n=104g+u][k]

// ============================ helpers ============================
__device__ __forceinline__ unsigned smem_u32(const void* p) {
    unsigned a;
    asm("{ .reg .u64 t; cvta.to.shared.u64 t, %1; cvt.u32.u64 %0, t; }" : "=r"(a) : "l"(p));
    return a;
}
__device__ __forceinline__ float fast_ex2(float x){ float y; asm("ex2.approx.f32 %0,%1;" : "=f"(y) : "f"(x)); return y; }
__device__ __forceinline__ float fast_rcp(float x){ float y; asm("rcp.approx.f32 %0,%1;" : "=f"(y) : "f"(x)); return y; }
__device__ __forceinline__ float fsigm(float x){ return fast_rcp(1.f + fast_ex2(-1.4426950408889634f * x)); }
__device__ __forceinline__ float htanh(float x){ float y; asm("tanh.approx.f32 %0,%1;" : "=f"(y) : "f"(x)); return y; }
__device__ __forceinline__ float tsigm(float x){ return fmaf(0.5f, htanh(0.5f * x), 0.5f); }

__device__ __forceinline__ void ldsm_x4(unsigned* r, unsigned addr) {
    asm volatile("ldmatrix.sync.aligned.m8n8.x4.shared.b16 {%0,%1,%2,%3}, [%4];"
        : "=r"(r[0]), "=r"(r[1]), "=r"(r[2]), "=r"(r[3]) : "r"(addr));
}
__device__ __forceinline__ void ldsm_x2(unsigned& r0, unsigned& r1, unsigned addr) {
    asm volatile("ldmatrix.sync.aligned.m8n8.x2.shared.b16 {%0,%1}, [%2];"
        : "=r"(r0), "=r"(r1) : "r"(addr));
}
__device__ __forceinline__ void ldsm_x1(unsigned& r0, unsigned addr) {
    asm volatile("ldmatrix.sync.aligned.m8n8.x1.shared.b16 {%0}, [%1];"
        : "=r"(r0) : "r"(addr));
}
__device__ __forceinline__ void mma16(float* c, const unsigned* a, unsigned b0, unsigned b1) {
    asm volatile("mma.sync.aligned.m16n8k16.row.col.f32.bf16.bf16.f32 "
        "{%0,%1,%2,%3}, {%4,%5,%6,%7}, {%8,%9}, {%0,%1,%2,%3};"
        : "+f"(c[0]), "+f"(c[1]), "+f"(c[2]), "+f"(c[3])
        : "r"(a[0]), "r"(a[1]), "r"(a[2]), "r"(a[3]), "r"(b0), "r"(b1));
}
__device__ __forceinline__ void mma8(float* c, unsigned a0, unsigned a1, unsigned b0) {
    asm volatile("mma.sync.aligned.m16n8k8.row.col.f32.bf16.bf16.f32 "
        "{%0,%1,%2,%3}, {%4,%5}, {%6}, {%0,%1,%2,%3};"
        : "+f"(c[0]), "+f"(c[1]), "+f"(c[2]), "+f"(c[3])
        : "r"(a0), "r"(a1), "r"(b0));
}

// ============================ setup: B image + proj + xk(fp32) ============================
__global__ void __launch_bounds__(256) setup_kernel(
    const float* __restrict__ z, const float* __restrict__ W1, const float* __restrict__ b1,
    const float* __restrict__ W2, const float* __restrict__ b2,
    const float* __restrict__ lstm_k, const float* __restrict__ lstm_r,
    const float* __restrict__ lstm_b)
{
    if (blockIdx.x >= 1024) {
        int i = (blockIdx.x - 1024) * 256 + threadIdx.x;
        if (i < NPADN * KEL) {
            int n = i / KEL, k = i % KEL;
            int g = n / 104, u = n % 104;
            float v = 0.f;
            if (u < 100) {
                int col = u + 100 * g;
                if (k < 100)      v = lstm_r[(size_t)k * 400 + col];
                else if (k < 102) v = lstm_k[(size_t)(50 + (k - 100)) * 400 + col];
            }
            g_Rimg[i] = __float2bfloat16_rn(v);
        }
        return;
    }
    const int warp = threadIdx.x >> 5, lane = threadIdx.x & 31;
    for (int b = blockIdx.x * 8 + warp; b < B_TOT; b += 8192) {
        float zr[4];
        #pragma unroll
        for (int q = 0; q < 4; q++) zr[q] = z[(size_t)b * 128 + q * 32 + lane];

        float a0 = b1[lane];
        float a1 = (lane < 18) ? b1[32 + lane] : 0.f;
        for (int i = 0; i < 128; i++) {
            float zi = __shfl_sync(0xffffffffu, zr[i >> 5], i & 31);
            a0 = fmaf(zi, W1[i * 50 + lane], a0);
            if (lane < 18) a1 = fmaf(zi, W1[i * 50 + 32 + lane], a1);
        }
        float p10 = fmaxf(a0, 0.f), p11 = fmaxf(a1, 0.f);

        float c0 = b2[lane];
        float c1 = (lane < 18) ? b2[32 + lane] : 0.f;
        for (int i = 0; i < 50; i++) {
            float pi = __shfl_sync(0xffffffffu, (i < 32) ? p10 : p11, i & 31);
            c0 = fmaf(pi, W2[i * 50 + lane], c0);
            if (lane < 18) c1 = fmaf(pi, W2[i * 50 + 32 + lane], c1);
        }
        float p20 = fmaxf(c0, 0.f), p21 = fmaxf(c1, 0.f);

        float acc[13];
        #pragma unroll
        for (int q = 0; q < 13; q++) { int j = lane + 32 * q; acc[q] = (j < 400) ? lstm_b[j] : 0.f; }
        for (int i = 0; i < 50; i++) {
            float pi = __shfl_sync(0xffffffffu, (i < 32) ? p20 : p21, i & 31);
            const float* kr = lstm_k + (size_t)i * 400;
            #pragma unroll
            for (int q = 0; q < 13; q++) { int j = lane + 32 * q; if (j < 400) acc[q] = fmaf(pi, kr[j], acc[q]); }
        }
        float* xo = g_xk + (size_t)b * 400;
        #pragma unroll
        for (int q = 0; q < 13; q++) {
            int j = lane + 32 * q;
            if (j < 400) xo[4 * (j % 100) + (j / 100)] = acc[q];
        }
    }
}

// ============================ rollout ============================
__global__ void __launch_bounds__(NTHR, 1) rollout_kernel(
    const float* __restrict__ idm_params, const float* __restrict__ idm_s,
    const float* __restrict__ sdv_acts,   const float* __restrict__ att_w,
    const float* __restrict__ att_b,      float* __restrict__ out)
{
    extern __shared__ char sm[];
    const unsigned sbase = smem_u32(sm);
    float* att_f = (float*)(sm + OFF_ATT);
    float* aw_f  = (float*)(sm + OFF_AW);

    const int tid = threadIdx.x, lane = tid & 31, wid = tid >> 5;
    const int b0 = blockIdx.x * MCH;

    // ---- phase 1: R image into temp region (OFF_XK), zero A bufs, aw ----
    {
        const uint4* src = (const uint4*)g_Rimg;
        uint4* dR = (uint4*)(sm + OFF_XK);
        for (int i = tid; i < 86528 / 16; i += NTHR) dR[i] = src[i];
        uint4 zz = make_uint4(0, 0, 0, 0);
        uint4* dA = (uint4*)(sm + OFF_A0);
        for (int i = tid; i < 53248 / 16; i += NTHR) dA[i] = zz;
        for (int i = tid; i < 100; i += NTHR) aw_f[i] = att_w[i];
    }
    __syncthreads();

    // ---- roles ----
    const int j = wid;                 // warp owns j-tile j (0..12)
    const int amat = lane >> 3;
    const int cg = lane >> 2, ct = lane & 3;
    const int bnr = lane & 7, bq = lane >> 3;

    // ---- phase 2: B fragments from R temp -> registers (live all 40 steps) ----
    unsigned bB[4][13];
    #pragma unroll
    for (int g = 0; g < 4; g++) {
        const unsigned baddr = sbase + OFF_XK + (unsigned)(104 * g + 8 * j + bnr) * ROWB;
        ldsm_x4(&bB[g][0], baddr + ((0 + bq) << 4));
        ldsm_x4(&bB[g][4], baddr + ((4 + bq) << 4));
        ldsm_x4(&bB[g][8], baddr + ((8 + bq) << 4));
        ldsm_x1(bB[g][12], baddr + 192u);
    }
    __syncthreads();

    // ---- phase 3: overwrite temp region with xk (bf16, stride 808 B) ----
    for (int idx = tid; idx < MCH * 200; idx += NTHR) {
        int row = idx / 200, p = idx % 200;
        const float2 xv = *(const float2*)(g_xk + (size_t)(b0 + row) * 400 + 2 * p);
        __nv_bfloat162 pk = __floats2bfloat162_rn(xv.x, xv.y);
        *(unsigned*)(sm + OFF_XK + row * XKB + p * 4) = *(unsigned*)&pk;
    }
    if (tid < MCH) {   // sdv(0) into A0 at k=100,101
        const float2 sd = *(const float2*)(sdv_acts + (size_t)(b0 + tid) * TST * 2);
        __nv_bfloat162 pk = __floats2bfloat162_rn(sd.x, sd.y);
        *(unsigned*)(sm + OFF_A0 + tid * ROWB + 200) = *(unsigned*)&pk;
    }

    float c_st[8][4];   // [mt][2ph+unit]
    #pragma unroll
    for (int a = 0; a < 8; a++)
        #pragma unroll
        for (int b = 0; b < 4; b++) c_st[a][b] = 0.f;

    float ego_v = 0.f, ego_x = 0.f;
    if (tid < MCH) {
        const float* s0p = idm_s + (size_t)(b0 + tid) * TST * 12;
        ego_v = s0p[0]; ego_x = s0p[3];
    }
    __syncthreads();

    const int u0 = 8 * j + 2 * ct;
    const float aw0 = (u0 < 100) ? aw_f[u0] : 0.f;
    const float aw1 = (u0 < 100) ? aw_f[u0 + 1] : 0.f;

    for (int t = 0; t < TST; t++) {
        const unsigned acur = (t & 1) ? OFF_A1 : OFF_A0;
        const unsigned anxt = (t & 1) ? OFF_A0 : OFF_A1;
        float* atb = att_f + (t & 1) * (13 * MCH);

        // prefetch this step's IDM inputs + stage sdv(t+1) (hidden under GEMM)
        float fv = 0.f, mv = 0.f, fx = 0.f, mx = 0.f, fex = 0.f, mex = 0.f;
        if (tid < MCH) {
            const float* srow = idm_s + ((size_t)(b0 + tid) * TST + t) * 12;
            fv = srow[1]; mv = srow[2]; fx = srow[4]; mx = srow[5];
            fex = srow[10]; mex = srow[11];
            if (t + 1 < TST) {
                const float2 sd = *(const float2*)(sdv_acts + ((size_t)(b0 + tid) * TST + t + 1) * 2);
                __nv_bfloat162 pk = __floats2bfloat162_rn(sd.x, sd.y);
                *(unsigned*)(sm + anxt + tid * ROWB + 200) = *(unsigned*)&pk;
            }
        }

        #pragma unroll
        for (int mt = 0; mt < 8; mt++) {
            // ---- A fragments for this 16-row m-tile ----
            unsigned afr[6][4], a80, a81;
            {
                const int arow = 16 * mt + (lane & 7) + ((amat & 1) << 3);
                const int akoff = amat >> 1;
                #pragma unroll
                for (int s = 0; s < 6; s++)
                    ldsm_x4(afr[s], sbase + acur + (unsigned)arow * ROWB + (unsigned)((2 * s + akoff) << 4));
                const int a8r = 16 * mt + (lane & 7) + (((lane >> 3) & 1) << 3);
                ldsm_x2(a80, a81, sbase + acur + (unsigned)a8r * ROWB + 192u);
            }

            float C[4][4];
            #pragma unroll
            for (int g = 0; g < 4; g++)
                #pragma unroll
                for (int q = 0; q < 4; q++) C[g][q] = 0.f;

            // g-interleaved MMA: 4 independent chains, B from registers
            #pragma unroll
            for (int s2 = 0; s2 < 3; s2++) {
                #pragma unroll
                for (int g = 0; g < 4; g++)
                    mma16(C[g], afr[2 * s2], bB[g][4 * s2], bB[g][4 * s2 + 1]);
                #pragma unroll
                for (int g = 0; g < 4; g++)
                    mma16(C[g], afr[2 * s2 + 1], bB[g][4 * s2 + 2], bB[g][4 * s2 + 3]);
            }
            #pragma unroll
            for (int g = 0; g < 4; g++)
                mma8(C[g], a80, a81, bB[g][12]);

            // ---- epilogue: gates in-thread; xk bf16 from SMEM; c in regs ----
            #pragma unroll
            for (int ph = 0; ph < 2; ph++) {
                float attp = 0.f;
                if (u0 < 100) {
                    const int row = 16 * mt + cg + 8 * ph;
                    const uint2 xkp = *(const uint2*)(sm + OFF_XK + row * XKB + u0 * 8);
                    const __nv_bfloat162 xa = *(const __nv_bfloat162*)&xkp.x;
                    const __nv_bfloat162 xb = *(const __nv_bfloat162*)&xkp.y;
                    float z0 = C[0][2 * ph] + __bfloat162float(xa.x);
                    float z1 = C[1][2 * ph] + __bfloat162float(xa.y);
                    float z2 = C[2][2 * ph] + __bfloat162float(xb.x);
                    float z3 = C[3][2 * ph] + __bfloat162float(xb.y);
                    float cn0 = tsigm(z1) * c_st[mt][2 * ph] + tsigm(z0) * htanh(z2);
                    c_st[mt][2 * ph] = cn0;
                    float h0 = htanh(cn0) * tsigm(z3);

                    const uint2 xkq = *(const uint2*)(sm + OFF_XK + row * XKB + u0 * 8 + 8);
                    const __nv_bfloat162 ya = *(const __nv_bfloat162*)&xkq.x;
                    const __nv_bfloat162 yb = *(const __nv_bfloat162*)&xkq.y;
                    float y0 = C[0][2 * ph + 1] + __bfloat162float(ya.x);
                    float y1 = C[1][2 * ph + 1] + __bfloat162float(ya.y);
                    float y2 = C[2][2 * ph + 1] + __bfloat162float(yb.x);
                    float y3 = C[3][2 * ph + 1] + __bfloat162float(yb.y);
                    float cn1 = tsigm(y1) * c_st[mt][2 * ph + 1] + tsigm(y0) * htanh(y2);
                    c_st[mt][2 * ph + 1] = cn1;
                    float h1 = htanh(cn1) * tsigm(y3);

                    attp = fmaf(h0, aw0, h1 * aw1);
                    __nv_bfloat162 pk = __floats2bfloat162_rn(h0, h1);
                    *(unsigned*)(sm + anxt + row * ROWB + u0 * 2) = *(unsigned*)&pk;
                }
                // reduce att partial over ct NOW (keeps register count flat)
                attp += __shfl_xor_sync(0xffffffffu, attp, 1);
                attp += __shfl_xor_sync(0xffffffffu, attp, 2);
                if (ct == 0) atb[j * MCH + 16 * mt + cg + 8 * ph] = attp;
            }
        }
        __syncthreads();   // the ONLY barrier per step

        // ---- IDM + integrate + store (threads 0..127); others proceed to t+1 ----
        if (tid < MCH) {
            const int b = b0 + tid;
            const float* pp = idm_params + b * 5;
            const float vdes = pp[0], tgap = pp[1], jamx = pp[2], amax = pp[3];
            const float gden = 2.f * sqrtf(amax * pp[4]);

            float s = 0.f;
            #pragma unroll
            for (int q = 0; q < 13; q++) s += atb[q * MCH + tid];
            float att = fsigm(s + att_b[0]);
            att = (fex * att + (1.f - fex)) * mex;

            float v = ego_v, x = ego_x;
            float dx1 = fminf(fmaxf(fx - x, 0.1f), 1000.f);
            float gap1 = tgap * v + v * (v - fv) / gden;
            float dg1 = jamx + fmaxf(gap1, 0.f);
            float r1 = v / vdes; float r1s = r1 * r1;
            float r2 = dg1 / dx1;
            float ef = amax * (1.f - r1s * r1s - r2 * r2);
            ef = fminf(fmaxf(ef, -100000.f), 100000.f);

            float dx2 = fminf(fmaxf(mx - x, 0.1f), 1000.f);
            float gap2 = tgap * v + v * (v - mv) / gden;
            float dg2 = jamx + fmaxf(gap2, 0.f);
            float r3 = dg2 / dx2;
            float em2 = amax * (1.f - r1s * r1s - r3 * r3);
            em2 = fminf(fmaxf(em2, -100000.f), 100000.f);

            float act = (1.f - att) * ef + att * em2;
            float vn = v + act * DT;
            ego_x = x + vn * DT + 0.5f * act * DT * DT;
            ego_v = vn;

            out[(size_t)b * TST + t] = act;
            out[(size_t)B_TOT * TST + (size_t)b * TST + t] = att;
        }
    }
}

// ============================ launch ============================
extern "C" void kernel_launch(void* const* d_in, const int* in_sizes, int n_in,
                              void* d_out, int out_size) {
    const float* sampled_z  = (const float*)d_in[0];
    const float* idm_params = (const float*)d_in[1];
    const float* idm_s      = (const float*)d_in[2];
    const float* sdv_acts   = (const float*)d_in[3];
    const float* W1         = (const float*)d_in[4];
    const float* b1         = (const float*)d_in[5];
    const float* W2         = (const float*)d_in[6];
    const float* b2         = (const float*)d_in[7];
    const float* lstm_k     = (const float*)d_in[8];
    const float* lstm_r     = (const float*)d_in[9];
    const float* lstm_b     = (const float*)d_in[10];
    const float* att_w      = (const float*)d_in[11];
    const float* att_b      = (const float*)d_in[12];
    float* out = (float*)d_out;

    cudaFuncSetAttribute(rollout_kernel, cudaFuncAttributeMaxDynamicSharedMemorySize, SMEM_BYTES);

    setup_kernel<<<1024 + (NPADN * KEL + 255) / 256, 256>>>(
        sampled_z, W1, b1, W2, b2, lstm_k, lstm_r, lstm_b);
    rollout_kernel<<<B_TOT / MCH, NTHR, SMEM_BYTES>>>(idm_params, idm_s, sdv_acts, att_w, att_b, out);
}